// round 14
// baseline (speedup 1.0000x reference)
#include <cuda_runtime.h>
#include <cuda_fp16.h>
#include <cstdint>

// Problem constants
#define NN   4096
#define DD   128
#define RR   8
#define OUTD 128
#define BB   4096

// Scratch (device globals: allocation-free)
__device__ float  g_Kt[(RR + 1) * DD * OUTD];       // [9][o][d] transposed kernels
__device__ __half g_Wh[(size_t)RR * OUTD * NN];     // [8][o][n]  W transposed (fp16)
__device__ float  g_P [(size_t)RR * NN * OUTD];     // [8][n][o]
__device__ float  g_S [(size_t)2 * OUTD * BB];      // [2][o][b]  self-kernel term

// ---------------------------------------------------------------- helpers ----
__device__ __forceinline__ uint32_t pack_h2(float lo, float hi) {
    uint32_t r;
    asm("cvt.rn.f16x2.f32 %0, %1, %2;" : "=r"(r) : "f"(hi), "f"(lo));
    return r;
}

__device__ __forceinline__ void ldm_x4(uint32_t* r, uint32_t addr) {
    asm volatile("ldmatrix.sync.aligned.m8n8.x4.shared.b16 {%0,%1,%2,%3}, [%4];"
                 : "=r"(r[0]), "=r"(r[1]), "=r"(r[2]), "=r"(r[3]) : "r"(addr));
}

__device__ __forceinline__ void mma16816(float* d, const uint32_t* a, const uint32_t* b) {
    asm volatile("mma.sync.aligned.m16n8k16.row.col.f32.f16.f16.f32 "
                 "{%0,%1,%2,%3}, {%4,%5,%6,%7}, {%8,%9}, {%0,%1,%2,%3};"
                 : "+f"(d[0]), "+f"(d[1]), "+f"(d[2]), "+f"(d[3])
                 : "r"(a[0]), "r"(a[1]), "r"(a[2]), "r"(a[3]),
                   "r"(b[0]), "r"(b[1]));
}

__device__ __forceinline__ void cp16(uint32_t smem_dst, const void* gmem_src) {
    asm volatile("cp.async.cg.shared.global [%0], [%1], 16;" :: "r"(smem_dst), "l"(gmem_src));
}

// ----------------- k0: transpose relk (8) + selfk (1) -> g_Kt[z][o][d] -------
__global__ void k0_transpose(const float* __restrict__ relk,
                             const float* __restrict__ selfk) {
    __shared__ float t[32][33];
    const int z = blockIdx.z;
    const float* src = (z < RR) ? (relk + (size_t)z * DD * OUTD) : selfk;
    const int bo = blockIdx.x * 32;
    const int bd = blockIdx.y * 32;
    const int tx = threadIdx.x, ty = threadIdx.y;

#pragma unroll
    for (int i = ty; i < 32; i += 8)
        t[i][tx] = src[(size_t)(bd + i) * OUTD + bo + tx];
    __syncthreads();
    float* dst = g_Kt + (size_t)z * DD * OUTD;
#pragma unroll
    for (int i = ty; i < 32; i += 8)
        dst[(size_t)(bo + i) * DD + bd + tx] = t[tx][i];
}

// ----------------- kH: generic 128x128-tile fp16 mma.sync GEMM ---------------
// C_tile[m][n] = sum_k A[m][k] * B[n][k]; fp32 in, fp32 acc, fp32 or fp16 out.
// blockIdx.z picks B0 (z=0) vs B1 (z=1); C shifted by cZ*z.
#define KB   32
#define ASTR 40
#define TILE_HALFS (128 * ASTR)

__global__ __launch_bounds__(256) void kH(
    const float* __restrict__ A0, size_t aY, size_t aX, int lda,
    const float* __restrict__ B0, const float* __restrict__ B1,
    size_t bY, size_t bX, int ldb,
    void* __restrict__ C0, size_t cY, size_t cX, size_t cZ, int ldc,
    int NC, int half_out) {
    __shared__ __align__(16) uint16_t sA[2][TILE_HALFS];
    __shared__ __align__(16) uint16_t sB[2][TILE_HALFS];

    const int tid  = threadIdx.x;
    const int warp = tid >> 5, lane = tid & 31;
    const int wm = warp & 3, wn = warp >> 2;
    const int gq = lane >> 2, tq = lane & 3;

    const float* A = A0 + blockIdx.y * aY + blockIdx.x * aX;
    const float* B = (blockIdx.z ? B1 : B0) + blockIdx.y * bY + blockIdx.x * bX;

    const int row0 = tid >> 3, c8 = tid & 7;
    const int q = lane >> 3, r8 = lane & 7;
    const uint32_t sAu = (uint32_t)__cvta_generic_to_shared(sA);
    const uint32_t sBu = (uint32_t)__cvta_generic_to_shared(sB);
    const uint32_t aAddr0 = sAu + (uint32_t)(((wm * 32 + (q & 1) * 8 + r8) * ASTR + (q >> 1) * 8) * 2);
    const uint32_t bAddr0 = sBu + (uint32_t)(((wn * 64 + (q >> 1) * 8 + r8) * ASTR + (q & 1) * 8) * 2);

    float acc[2][8][4];
#pragma unroll
    for (int i = 0; i < 2; i++)
#pragma unroll
        for (int j = 0; j < 8; j++)
#pragma unroll
            for (int v = 0; v < 4; v++) acc[i][j][v] = 0.f;

    float4 aR[4], bR[4];

#define GLOAD(m)                                                              \
    do {                                                                      \
        const float* ap = A + (size_t)row0 * lda + (m) * KB + c8 * 4;         \
        const float* bp = B + (size_t)row0 * ldb + (m) * KB + c8 * 4;         \
        _Pragma("unroll")                                                     \
        for (int i = 0; i < 4; i++) {                                         \
            aR[i] = *(const float4*)(ap + (size_t)(i * 32) * lda);            \
            bR[i] = *(const float4*)(bp + (size_t)(i * 32) * ldb);            \
        }                                                                     \
    } while (0)

#define CSTORE(buf)                                                           \
    do {                                                                      \
        _Pragma("unroll")                                                     \
        for (int i = 0; i < 4; i++) {                                         \
            const int off = (row0 + i * 32) * ASTR + c8 * 4;                  \
            *(uint2*)&sA[buf][off] =                                          \
                make_uint2(pack_h2(aR[i].x, aR[i].y), pack_h2(aR[i].z, aR[i].w)); \
            *(uint2*)&sB[buf][off] =                                          \
                make_uint2(pack_h2(bR[i].x, bR[i].y), pack_h2(bR[i].z, bR[i].w)); \
        }                                                                     \
    } while (0)

    GLOAD(0);

    for (int m = 0; m < NC; m++) {
        const int buf = m & 1;
        CSTORE(buf);
        __syncthreads();
        if (m + 1 < NC) GLOAD(m + 1);

        const uint32_t aB = aAddr0 + buf * (TILE_HALFS * 2);
        const uint32_t bB = bAddr0 + buf * (TILE_HALFS * 2);
#pragma unroll
        for (int ks = 0; ks < 2; ks++) {
            uint32_t af[2][4];
#pragma unroll
            for (int i = 0; i < 2; i++)
                ldm_x4(af[i], aB + i * (16 * ASTR * 2) + ks * 32);
            uint32_t bf[4][4];
#pragma unroll
            for (int jp = 0; jp < 4; jp++)
                ldm_x4(bf[jp], bB + jp * (16 * ASTR * 2) + ks * 32);
#pragma unroll
            for (int i = 0; i < 2; i++)
#pragma unroll
                for (int j = 0; j < 8; j++)
                    mma16816(acc[i][j], af[i], &bf[j >> 1][(j & 1) * 2]);
        }
        __syncthreads();
    }

    // epilogue
    if (half_out) {
        __half* C = (__half*)C0 + blockIdx.y * cY + blockIdx.x * cX + blockIdx.z * cZ;
#pragma unroll
        for (int i = 0; i < 2; i++) {
            const int row = wm * 32 + i * 16 + gq;
#pragma unroll
            for (int j = 0; j < 8; j++) {
                const int col = wn * 64 + j * 8 + tq * 2;
                *(uint32_t*)(C + (size_t)row * ldc + col)       = pack_h2(acc[i][j][0], acc[i][j][1]);
                *(uint32_t*)(C + (size_t)(row + 8) * ldc + col) = pack_h2(acc[i][j][2], acc[i][j][3]);
            }
        }
    } else {
        float* C = (float*)C0 + blockIdx.y * cY + blockIdx.x * cX + blockIdx.z * cZ;
#pragma unroll
        for (int i = 0; i < 2; i++) {
            const int row = wm * 32 + i * 16 + gq;
#pragma unroll
            for (int j = 0; j < 8; j++) {
                const int col = wn * 64 + j * 8 + tq * 2;
                *(float2*)(C + (size_t)row * ldc + col)       = make_float2(acc[i][j][0], acc[i][j][1]);
                *(float2*)(C + (size_t)(row + 8) * ldc + col) = make_float2(acc[i][j][2], acc[i][j][3]);
            }
        }
    }
}

// ----------------- kP: P[r][m][o] = adj_r @ Wh_r^T  ---------------------------
// A: direct LDG->fragment (fp32->fp16 in regs, 1-step prefetch).
// B: fp16 via 4-stage cp.async ring. One __syncthreads per K=64 chunk.
#define KBP  64
#define NCH  64
#define BSTR 72                         // halves per B smem row (144B, conflict-free)
#define BSTAGE_HALFS (128 * BSTR)       // 9216 halves = 18432 B per stage
#define KP_SMEM (4 * BSTAGE_HALFS * 2)  // 73728 B dynamic

__global__ __launch_bounds__(256, 2) void kP(const float* __restrict__ adj,
                                             const __half* __restrict__ Wh,
                                             float* __restrict__ P) {
    extern __shared__ __align__(16) uint16_t sB[];

    const int tid  = threadIdx.x;
    const int warp = tid >> 5, lane = tid & 31;
    const int wm = warp & 3, wn = warp >> 2;
    const int gq = lane >> 2, tq = lane & 3;

    const int mt = blockIdx.x, r = blockIdx.y;
    // A: per-thread fragment base (row = mt*128 + wm*32 + gq, col = tq*2)
    const float* Ab = adj + (size_t)r * NN * NN
                    + (size_t)(mt * 128 + wm * 32 + gq) * NN + tq * 2;
    const __half* B = Wh + (size_t)r * OUTD * NN;
    float* C = P + (size_t)r * NN * OUTD + (size_t)mt * 128 * OUTD;

    const uint32_t sBu = (uint32_t)__cvta_generic_to_shared(sB);

    // B cp.async geometry: row = tid>>1 (o), half-block = tid&1 covers halves [hb*32, hb*32+32)
    const int rowB = tid >> 1, hb = tid & 1;
    const uint32_t bDst0 = sBu + (uint32_t)((rowB * BSTR + hb * 32) * 2);
    const __half*  bSrc0 = B + (size_t)rowB * NN + hb * 32;

    // B ldmatrix geometry
    const int q2 = lane >> 3, r8 = lane & 7;
    const uint32_t bAddr0 = sBu + (uint32_t)(((wn * 64 + (q2 >> 1) * 8 + r8) * BSTR + (q2 & 1) * 8) * 2);

    float acc[2][8][4];
#pragma unroll
    for (int i = 0; i < 2; i++)
#pragma unroll
        for (int j = 0; j < 8; j++)
#pragma unroll
            for (int v = 0; v < 4; v++) acc[i][j][v] = 0.f;

    float2 pre[8];

    // load A fragments for linearized step s (koff = s*16), wrap-guarded
#define LDA(s)                                                                \
    do {                                                                      \
        const float* p = Ab + (((s) & 255) << 4);                             \
        pre[0] = *(const float2*)(p);                                         \
        pre[1] = *(const float2*)(p + 8 * NN);                                \
        pre[2] = *(const float2*)(p + 8);                                     \
        pre[3] = *(const float2*)(p + 8 * NN + 8);                            \
        pre[4] = *(const float2*)(p + 16 * NN);                               \
        pre[5] = *(const float2*)(p + 24 * NN);                               \
        pre[6] = *(const float2*)(p + 16 * NN + 8);                           \
        pre[7] = *(const float2*)(p + 24 * NN + 8);                           \
    } while (0)

#define CPB(m, slot)                                                          \
    do {                                                                      \
        const uint32_t d = bDst0 + (slot) * (BSTAGE_HALFS * 2);               \
        const __half* s = bSrc0 + (size_t)(m) * KBP;                          \
        cp16(d, s); cp16(d + 16, s + 8);                                      \
        cp16(d + 32, s + 16); cp16(d + 48, s + 24);                           \
        asm volatile("cp.async.commit_group;");                               \
    } while (0)

    // prologue: stage chunks 0..2, prefetch A step 0
    CPB(0, 0);
    CPB(1, 1);
    CPB(2, 2);
    LDA(0);

    for (int m = 0; m < NCH; m++) {
        asm volatile("cp.async.wait_group 2;");
        __syncthreads();                       // chunk m visible; all warps done with m-1
        if (m + 3 < NCH) {
            CPB(m + 3, (m + 3) & 3);
        } else {
            asm volatile("cp.async.commit_group;");   // keep pending-count invariant
        }

        const uint32_t bB = bAddr0 + (m & 3) * (BSTAGE_HALFS * 2);
#pragma unroll
        for (int ks = 0; ks < 4; ks++) {
            uint32_t af[2][4];
            af[0][0] = pack_h2(pre[0].x, pre[0].y);
            af[0][1] = pack_h2(pre[1].x, pre[1].y);
            af[0][2] = pack_h2(pre[2].x, pre[2].y);
            af[0][3] = pack_h2(pre[3].x, pre[3].y);
            af[1][0] = pack_h2(pre[4].x, pre[4].y);
            af[1][1] = pack_h2(pre[5].x, pre[5].y);
            af[1][2] = pack_h2(pre[6].x, pre[6].y);
            af[1][3] = pack_h2(pre[7].x, pre[7].y);
            LDA(m * 4 + ks + 1);

            uint32_t bf[4][4];
#pragma unroll
            for (int jp = 0; jp < 4; jp++)
                ldm_x4(bf[jp], bB + jp * (16 * BSTR * 2) + ks * 32);
#pragma unroll
            for (int i = 0; i < 2; i++)
#pragma unroll
                for (int j = 0; j < 8; j++)
                    mma16816(acc[i][j], af[i], &bf[j >> 1][(j & 1) * 2]);
        }
    }

#pragma unroll
    for (int i = 0; i < 2; i++) {
        const int row = wm * 32 + i * 16 + gq;
#pragma unroll
        for (int j = 0; j < 8; j++) {
            const int col = wn * 64 + j * 8 + tq * 2;
            *(float2*)(C + (size_t)row * OUTD + col)       = make_float2(acc[i][j][0], acc[i][j][1]);
            *(float2*)(C + (size_t)(row + 8) * OUTD + col) = make_float2(acc[i][j][2], acc[i][j][3]);
        }
    }
}

// ----------------- k3: out[br][b][o] = S[br][o][b] + sum_r P[r][idx[b]][o] ---
__global__ __launch_bounds__(256) void k3_gather(const int* __restrict__ hi,
                                                 const int* __restrict__ ti,
                                                 float* __restrict__ out) {
    __shared__ int idxs[64];
    const int br = blockIdx.y;
    const int* idx = br ? ti : hi;
    const int b0 = blockIdx.x * 64;
    const int tid = threadIdx.x;
    if (tid < 64) idxs[tid] = idx[b0 + tid];
    __syncthreads();

    const int o  = tid & 127;
    const int bh = tid >> 7;

    const float* Sp = g_S + (size_t)br * OUTD * BB + (size_t)o * BB + b0 + bh * 32;
    float sv[32];
#pragma unroll
    for (int qv = 0; qv < 8; qv++) {
        float4 v = *(const float4*)(Sp + qv * 4);
        sv[qv * 4 + 0] = v.x; sv[qv * 4 + 1] = v.y;
        sv[qv * 4 + 2] = v.z; sv[qv * 4 + 3] = v.w;
    }

#pragma unroll
    for (int bb = 0; bb < 32; bb++) {
        const int bl = bh * 32 + bb;
        const int id = idxs[bl];
        const float* Pp = g_P + (size_t)id * OUTD + o;
        float s = sv[bb];
#pragma unroll
        for (int rr2 = 0; rr2 < RR; rr2++)
            s += Pp[(size_t)rr2 * NN * OUTD];
        out[((size_t)br * BB + b0 + bl) * OUTD + o] = s;
    }
}

// ---------------- launch ------------------------------------------------------
extern "C" void kernel_launch(void* const* d_in, const int* in_sizes, int n_in,
                              void* d_out, int out_size) {
    const float* emb   = (const float*)d_in[0];
    const int*   hidx  = (const int*)  d_in[1];
    const float* he    = (const float*)d_in[2];
    const int*   tidx  = (const int*)  d_in[3];
    const float* te    = (const float*)d_in[4];
    const float* adj   = (const float*)d_in[5];
    const float* relk  = (const float*)d_in[6];
    const float* selfk = (const float*)d_in[7];
    float* out = (float*)d_out;

    void *pKt, *pWh, *pP, *pS;
    cudaGetSymbolAddress(&pKt, g_Kt);
    cudaGetSymbolAddress(&pWh, g_Wh);
    cudaGetSymbolAddress(&pP,  g_P);
    cudaGetSymbolAddress(&pS,  g_S);
    const float* Kt = (const float*)pKt;
    __half* Wh = (__half*)pWh;
    float* P  = (float*)pP;
    float* S  = (float*)pS;

    cudaFuncSetAttribute(kP, cudaFuncAttributeMaxDynamicSharedMemorySize, KP_SMEM);

    // 0) transpose kernels -> Kt[z][o][d]
    k0_transpose<<<dim3(4, 4, RR + 1), dim3(32, 8)>>>(relk, selfk);

    // 1) Wh[r][o][n] = Kt_r @ emb^T  (fp16 output)
    kH<<<dim3(NN / 128, RR, 1), 256>>>(
        Kt, (size_t)DD * OUTD, 0, DD,
        emb, emb, 0, (size_t)128 * DD, DD,
        Wh, (size_t)OUTD * NN, 128, 0, NN,
        4, 1);

    // 2) P[r][m][o] = adj_r @ Wh_r^T  (occupancy-2, A-direct, 4-stage B ring)
    kP<<<dim3(NN / 128, RR), 256, KP_SMEM>>>(adj, Wh, P);

    // 3) S[br][o][b] = SKt @ e^T  (both branches, one launch via blockIdx.z)
    kH<<<dim3(BB / 128, 1, 2), 256>>>(
        Kt + (size_t)RR * DD * OUTD, 0, 0, DD,
        he, te, 0, (size_t)128 * DD, DD,
        S, 0, 128, (size_t)OUTD * BB, BB,
        4, 0);

    // 4) gather + add
    k3_gather<<<dim3(BB / 64, 2), 256>>>(hidx, tidx, out);
}

// round 15
// speedup vs baseline: 1.4200x; 1.4200x over previous
#include <cuda_runtime.h>
#include <cuda_fp16.h>
#include <cstdint>

// Problem constants
#define NN   4096
#define DD   128
#define RR   8
#define OUTD 128
#define BB   4096

// Scratch (device globals: allocation-free)
__device__ float  g_Kt[(RR + 1) * DD * OUTD];       // [9][o][d] transposed kernels
__device__ __half g_Wh[(size_t)RR * OUTD * NN];     // [8][o][n]  W transposed (fp16)
__device__ float  g_P [(size_t)RR * NN * OUTD];     // [8][n][o]
__device__ float  g_S [(size_t)2 * OUTD * BB];      // [2][o][b]  self-kernel term

// ---------------------------------------------------------------- helpers ----
__device__ __forceinline__ uint32_t pack_h2(float lo, float hi) {
    uint32_t r;
    asm("cvt.rn.f16x2.f32 %0, %1, %2;" : "=r"(r) : "f"(hi), "f"(lo));
    return r;
}

__device__ __forceinline__ void ldm_x4(uint32_t* r, uint32_t addr) {
    asm volatile("ldmatrix.sync.aligned.m8n8.x4.shared.b16 {%0,%1,%2,%3}, [%4];"
                 : "=r"(r[0]), "=r"(r[1]), "=r"(r[2]), "=r"(r[3]) : "r"(addr));
}

__device__ __forceinline__ void mma16816(float* d, const uint32_t* a, const uint32_t* b) {
    asm volatile("mma.sync.aligned.m16n8k16.row.col.f32.f16.f16.f32 "
                 "{%0,%1,%2,%3}, {%4,%5,%6,%7}, {%8,%9}, {%0,%1,%2,%3};"
                 : "+f"(d[0]), "+f"(d[1]), "+f"(d[2]), "+f"(d[3])
                 : "r"(a[0]), "r"(a[1]), "r"(a[2]), "r"(a[3]),
                   "r"(b[0]), "r"(b[1]));
}

__device__ __forceinline__ void cp16(uint32_t smem_dst, const void* gmem_src) {
    asm volatile("cp.async.cg.shared.global [%0], [%1], 16;" :: "r"(smem_dst), "l"(gmem_src));
}

// ----------------- k0: transpose relk (8) + selfk (1) -> g_Kt[z][o][d] -------
__global__ void k0_transpose(const float* __restrict__ relk,
                             const float* __restrict__ selfk) {
    __shared__ float t[32][33];
    const int z = blockIdx.z;
    const float* src = (z < RR) ? (relk + (size_t)z * DD * OUTD) : selfk;
    const int bo = blockIdx.x * 32;
    const int bd = blockIdx.y * 32;
    const int tx = threadIdx.x, ty = threadIdx.y;

#pragma unroll
    for (int i = ty; i < 32; i += 8)
        t[i][tx] = src[(size_t)(bd + i) * OUTD + bo + tx];
    __syncthreads();
    float* dst = g_Kt + (size_t)z * DD * OUTD;
#pragma unroll
    for (int i = ty; i < 32; i += 8)
        dst[(size_t)(bo + i) * DD + bd + tx] = t[tx][i];
}

// ----------------- kSmall: fused Wt + S GEMMs (one launch, 320 CTAs) ---------
// grid (32, 10):
//   y in [0,8):  Wh[y][o][x*128+n] = Kt_y @ emb^T      (fp16 out, ldc=NN)
//   y == 8:      S[0][o][x*128+b] = SKt @ he^T          (fp32 out, ldc=BB)
//   y == 9:      S[1][o][x*128+b] = SKt @ te^T          (fp32 out, ldc=BB)
// All: M=o=128, K=d=128 (NC=4 chunks of 32), A row-major lda=DD, B rows lda=DD.
#define KB   32
#define ASTR 40
#define TILE_HALFS (128 * ASTR)

__global__ __launch_bounds__(256) void kSmall(const float* __restrict__ emb,
                                              const float* __restrict__ he,
                                              const float* __restrict__ te) {
    __shared__ __align__(16) uint16_t sA[2][TILE_HALFS];
    __shared__ __align__(16) uint16_t sB[2][TILE_HALFS];

    const int tid  = threadIdx.x;
    const int warp = tid >> 5, lane = tid & 31;
    const int wm = warp & 3, wn = warp >> 2;
    const int gq = lane >> 2, tq = lane & 3;
    const int x = blockIdx.x, y = blockIdx.y;

    const float* A;
    const float* B;
    if (y < RR) {
        A = g_Kt + (size_t)y * DD * OUTD;
        B = emb + (size_t)x * 128 * DD;
    } else {
        A = g_Kt + (size_t)RR * DD * OUTD;
        B = (y == RR ? he : te) + (size_t)x * 128 * DD;
    }

    const int row0 = tid >> 3, c8 = tid & 7;
    const int q = lane >> 3, r8 = lane & 7;
    const uint32_t sAu = (uint32_t)__cvta_generic_to_shared(sA);
    const uint32_t sBu = (uint32_t)__cvta_generic_to_shared(sB);
    const uint32_t aAddr0 = sAu + (uint32_t)(((wm * 32 + (q & 1) * 8 + r8) * ASTR + (q >> 1) * 8) * 2);
    const uint32_t bAddr0 = sBu + (uint32_t)(((wn * 64 + (q >> 1) * 8 + r8) * ASTR + (q & 1) * 8) * 2);

    float acc[2][8][4];
#pragma unroll
    for (int i = 0; i < 2; i++)
#pragma unroll
        for (int j = 0; j < 8; j++)
#pragma unroll
            for (int v = 0; v < 4; v++) acc[i][j][v] = 0.f;

    float4 aR[4], bR[4];

#define GLOAD(m)                                                              \
    do {                                                                      \
        const float* ap = A + (size_t)row0 * DD + (m) * KB + c8 * 4;          \
        const float* bp = B + (size_t)row0 * DD + (m) * KB + c8 * 4;          \
        _Pragma("unroll")                                                     \
        for (int i = 0; i < 4; i++) {                                         \
            aR[i] = *(const float4*)(ap + (size_t)(i * 32) * DD);             \
            bR[i] = *(const float4*)(bp + (size_t)(i * 32) * DD);             \
        }                                                                     \
    } while (0)

#define CSTORE(buf)                                                           \
    do {                                                                      \
        _Pragma("unroll")                                                     \
        for (int i = 0; i < 4; i++) {                                         \
            const int off = (row0 + i * 32) * ASTR + c8 * 4;                  \
            *(uint2*)&sA[buf][off] =                                          \
                make_uint2(pack_h2(aR[i].x, aR[i].y), pack_h2(aR[i].z, aR[i].w)); \
            *(uint2*)&sB[buf][off] =                                          \
                make_uint2(pack_h2(bR[i].x, bR[i].y), pack_h2(bR[i].z, bR[i].w)); \
        }                                                                     \
    } while (0)

    GLOAD(0);

    for (int m = 0; m < 4; m++) {
        const int buf = m & 1;
        CSTORE(buf);
        __syncthreads();
        if (m + 1 < 4) GLOAD(m + 1);

        const uint32_t aB = aAddr0 + buf * (TILE_HALFS * 2);
        const uint32_t bB = bAddr0 + buf * (TILE_HALFS * 2);
#pragma unroll
        for (int ks = 0; ks < 2; ks++) {
            uint32_t af[2][4];
#pragma unroll
            for (int i = 0; i < 2; i++)
                ldm_x4(af[i], aB + i * (16 * ASTR * 2) + ks * 32);
            uint32_t bf[4][4];
#pragma unroll
            for (int jp = 0; jp < 4; jp++)
                ldm_x4(bf[jp], bB + jp * (16 * ASTR * 2) + ks * 32);
#pragma unroll
            for (int i = 0; i < 2; i++)
#pragma unroll
                for (int j = 0; j < 8; j++)
                    mma16816(acc[i][j], af[i], &bf[j >> 1][(j & 1) * 2]);
        }
        __syncthreads();
    }

    // epilogue
    if (y < RR) {
        __half* C = g_Wh + (size_t)y * OUTD * NN + (size_t)x * 128;
#pragma unroll
        for (int i = 0; i < 2; i++) {
            const int row = wm * 32 + i * 16 + gq;
#pragma unroll
            for (int j = 0; j < 8; j++) {
                const int col = wn * 64 + j * 8 + tq * 2;
                *(uint32_t*)(C + (size_t)row * NN + col)       = pack_h2(acc[i][j][0], acc[i][j][1]);
                *(uint32_t*)(C + (size_t)(row + 8) * NN + col) = pack_h2(acc[i][j][2], acc[i][j][3]);
            }
        }
    } else {
        float* C = g_S + (size_t)(y - RR) * OUTD * BB + (size_t)x * 128;
#pragma unroll
        for (int i = 0; i < 2; i++) {
            const int row = wm * 32 + i * 16 + gq;
#pragma unroll
            for (int j = 0; j < 8; j++) {
                const int col = wn * 64 + j * 8 + tq * 2;
                *(float2*)(C + (size_t)row * BB + col)       = make_float2(acc[i][j][0], acc[i][j][1]);
                *(float2*)(C + (size_t)(row + 8) * BB + col) = make_float2(acc[i][j][2], acc[i][j][3]);
            }
        }
    }
}

// ----------------- kP: P[r][m][o] = adj_r @ Wh_r^T  (R13 proven version) -----
// A = adj fp32 (reg convert), B = Wh fp16 (cp.async, FULL tile: 2 x 16B/thread).
#define NCP 128

__global__ __launch_bounds__(256, 2) void kP(const float* __restrict__ adj,
                                             const __half* __restrict__ Wh,
                                             float* __restrict__ P) {
    __shared__ __align__(16) uint16_t sA[2][TILE_HALFS];
    __shared__ __align__(16) uint16_t sB[2][TILE_HALFS];

    const int tid  = threadIdx.x;
    const int warp = tid >> 5, lane = tid & 31;
    const int wm = warp & 3, wn = warp >> 2;
    const int gq = lane >> 2, tq = lane & 3;

    const int mt = blockIdx.x, r = blockIdx.y;
    const float*  A = adj + (size_t)r * NN * NN + (size_t)mt * 128 * NN;
    const __half* B = Wh + (size_t)r * OUTD * NN;
    float*        C = P + (size_t)r * NN * OUTD + (size_t)mt * 128 * OUTD;

    const int row0 = tid >> 3, c8 = tid & 7;       // A geometry
    const int rowB = tid >> 1, bseg = tid & 1;     // B cp.async geometry (2 x 16B)

    const int q = lane >> 3, r8 = lane & 7;
    const uint32_t sAu = (uint32_t)__cvta_generic_to_shared(sA);
    const uint32_t sBu = (uint32_t)__cvta_generic_to_shared(sB);
    const uint32_t aAddr0 = sAu + (uint32_t)(((wm * 32 + (q & 1) * 8 + r8) * ASTR + (q >> 1) * 8) * 2);
    const uint32_t bAddr0 = sBu + (uint32_t)(((wn * 64 + (q >> 1) * 8 + r8) * ASTR + (q & 1) * 8) * 2);
    const uint32_t bDst0  = sBu + (uint32_t)((rowB * ASTR + bseg * 16) * 2);
    const __half*  bSrc0  = B + (size_t)rowB * NN + bseg * 16;

    float acc[2][8][4];
#pragma unroll
    for (int i = 0; i < 2; i++)
#pragma unroll
        for (int j = 0; j < 8; j++)
#pragma unroll
            for (int v = 0; v < 4; v++) acc[i][j][v] = 0.f;

    float4 aR[4];

#define GLOADA(m)                                                             \
    do {                                                                      \
        const float* ap = A + (size_t)row0 * NN + (m) * KB + c8 * 4;          \
        _Pragma("unroll")                                                     \
        for (int i = 0; i < 4; i++)                                           \
            aR[i] = *(const float4*)(ap + (size_t)(i * 32) * NN);             \
    } while (0)

#define CSTA(buf)                                                             \
    do {                                                                      \
        _Pragma("unroll")                                                     \
        for (int i = 0; i < 4; i++) {                                         \
            const int off = (row0 + i * 32) * ASTR + c8 * 4;                  \
            *(uint2*)&sA[buf][off] =                                          \
                make_uint2(pack_h2(aR[i].x, aR[i].y), pack_h2(aR[i].z, aR[i].w)); \
        }                                                                     \
    } while (0)

#define CPB(m, buf)                                                           \
    do {                                                                      \
        cp16(bDst0 + (buf) * (TILE_HALFS * 2), bSrc0 + (m) * KB);             \
        cp16(bDst0 + 16 + (buf) * (TILE_HALFS * 2), bSrc0 + (m) * KB + 8);    \
        asm volatile("cp.async.commit_group;");                               \
    } while (0)

    GLOADA(0);
    CPB(0, 0);

    for (int m = 0; m < NCP; m++) {
        const int buf = m & 1;
        CSTA(buf);
        if (m + 1 < NCP) {
            GLOADA(m + 1);
            CPB(m + 1, buf ^ 1);
            asm volatile("cp.async.wait_group 1;");
        } else {
            asm volatile("cp.async.wait_group 0;");
        }
        __syncthreads();

        const uint32_t aB = aAddr0 + buf * (TILE_HALFS * 2);
        const uint32_t bB = bAddr0 + buf * (TILE_HALFS * 2);
#pragma unroll
        for (int ks = 0; ks < 2; ks++) {
            uint32_t af[2][4];
#pragma unroll
            for (int i = 0; i < 2; i++)
                ldm_x4(af[i], aB + i * (16 * ASTR * 2) + ks * 32);
            uint32_t bf[4][4];
#pragma unroll
            for (int jp = 0; jp < 4; jp++)
                ldm_x4(bf[jp], bB + jp * (16 * ASTR * 2) + ks * 32);
#pragma unroll
            for (int i = 0; i < 2; i++)
#pragma unroll
                for (int j = 0; j < 8; j++)
                    mma16816(acc[i][j], af[i], &bf[j >> 1][(j & 1) * 2]);
        }
        __syncthreads();
    }

#pragma unroll
    for (int i = 0; i < 2; i++) {
        const int row = wm * 32 + i * 16 + gq;
#pragma unroll
        for (int j = 0; j < 8; j++) {
            const int col = wn * 64 + j * 8 + tq * 2;
            *(float2*)(C + (size_t)row * OUTD + col)       = make_float2(acc[i][j][0], acc[i][j][1]);
            *(float2*)(C + (size_t)(row + 8) * OUTD + col) = make_float2(acc[i][j][2], acc[i][j][3]);
        }
    }
}

// ----------------- k3: out[br][b][o] = S[br][o][b] + sum_r P[r][idx[b]][o] ---
__global__ __launch_bounds__(256) void k3_gather(const int* __restrict__ hi,
                                                 const int* __restrict__ ti,
                                                 float* __restrict__ out) {
    __shared__ int idxs[64];
    const int br = blockIdx.y;
    const int* idx = br ? ti : hi;
    const int b0 = blockIdx.x * 64;
    const int tid = threadIdx.x;
    if (tid < 64) idxs[tid] = idx[b0 + tid];
    __syncthreads();

    const int o  = tid & 127;
    const int bh = tid >> 7;

    const float* Sp = g_S + (size_t)br * OUTD * BB + (size_t)o * BB + b0 + bh * 32;
    float sv[32];
#pragma unroll
    for (int qv = 0; qv < 8; qv++) {
        float4 v = *(const float4*)(Sp + qv * 4);
        sv[qv * 4 + 0] = v.x; sv[qv * 4 + 1] = v.y;
        sv[qv * 4 + 2] = v.z; sv[qv * 4 + 3] = v.w;
    }

#pragma unroll
    for (int bb = 0; bb < 32; bb++) {
        const int bl = bh * 32 + bb;
        const int id = idxs[bl];
        const float* Pp = g_P + (size_t)id * OUTD + o;
        float s = sv[bb];
#pragma unroll
        for (int rr2 = 0; rr2 < RR; rr2++)
            s += Pp[(size_t)rr2 * NN * OUTD];
        out[((size_t)br * BB + b0 + bl) * OUTD + o] = s;
    }
}

// ---------------- launch ------------------------------------------------------
extern "C" void kernel_launch(void* const* d_in, const int* in_sizes, int n_in,
                              void* d_out, int out_size) {
    const float* emb   = (const float*)d_in[0];
    const int*   hidx  = (const int*)  d_in[1];
    const float* he    = (const float*)d_in[2];
    const int*   tidx  = (const int*)  d_in[3];
    const float* te    = (const float*)d_in[4];
    const float* adj   = (const float*)d_in[5];
    const float* relk  = (const float*)d_in[6];
    const float* selfk = (const float*)d_in[7];
    float* out = (float*)d_out;

    void *pWh, *pP;
    cudaGetSymbolAddress(&pWh, g_Wh);
    cudaGetSymbolAddress(&pP,  g_P);
    __half* Wh = (__half*)pWh;
    float* P  = (float*)pP;

    // 0) transpose kernels -> Kt[z][o][d]
    k0_transpose<<<dim3(4, 4, RR + 1), dim3(32, 8)>>>(relk, selfk);

    // 1) fused small GEMMs: Wh (y<8) + S-he (y=8) + S-te (y=9), one launch
    kSmall<<<dim3(NN / 128, RR + 2), 256>>>(emb, he, te);

    // 2) P[r][m][o] = adj_r @ Wh_r^T  (occupancy-2)
    kP<<<dim3(NN / 128, RR), 256>>>(adj, Wh, P);

    // 3) gather + add
    k3_gather<<<dim3(BB / 64, 2), 256>>>(hidx, tidx, out);
}